// round 1
// baseline (speedup 1.0000x reference)
#include <cuda_runtime.h>
#include <cstdint>

// Problem constants
#define NB 8
#define RR 256
#define CI 64
#define CO 64
#define MD 16
#define KXN 32  // 16 top + 16 bottom kx modes

// ---------------------------------------------------------------------------
// Scratch (device globals -- no allocation allowed)
// ---------------------------------------------------------------------------
__device__ float2 g_A[NB * MD * RR * CI];   // [b][ky][u][i]   16.8 MB
__device__ float2 g_F[NB * KXN * MD * CI];  // [b][kx][ky][i]   2.1 MB
__device__ float2 g_G[NB * KXN * MD * CO];  // [b][kx][ky][o]   2.1 MB
__device__ float2 g_H[NB * MD * RR * CO];   // [b][ky][u][o]   16.8 MB

// ---------------------------------------------------------------------------
// Packed f32x2 helpers (Blackwell dual-FP32 pipe; only reachable via PTX)
// ---------------------------------------------------------------------------
__device__ __forceinline__ unsigned long long pack2(float lo, float hi) {
    unsigned long long r;
    asm("mov.b64 %0, {%1,%2};" : "=l"(r) : "f"(lo), "f"(hi));
    return r;
}
__device__ __forceinline__ unsigned long long fma2(unsigned long long a,
                                                   unsigned long long b,
                                                   unsigned long long c) {
    unsigned long long r;
    asm("fma.rn.f32x2 %0, %1, %2, %3;" : "=l"(r) : "l"(a), "l"(b), "l"(c));
    return r;
}
__device__ __forceinline__ unsigned long long add2(unsigned long long a,
                                                   unsigned long long b) {
    unsigned long long r;
    asm("add.rn.f32x2 %0, %1, %2;" : "=l"(r) : "l"(a), "l"(b));
    return r;
}
__device__ __forceinline__ void unpack2(unsigned long long v, float& lo, float& hi) {
    asm("mov.b64 {%0,%1}, %2;" : "=f"(lo), "=f"(hi) : "l"(v));
}

__device__ __forceinline__ float silu_f(float x) {
    float e = __expf(-x);
    return __fdividef(x, 1.0f + e);
}

// ---------------------------------------------------------------------------
// K1: partial column DFT along v for ky = 0..15.
// A[b][ky][u][i] = sum_v X[b,u,v,i] * exp(-2*pi*i*ky*v/256)
// Uses v <-> 256-v symmetry: shared sum/diff across all ky.
// ---------------------------------------------------------------------------
__global__ __launch_bounds__(256) void k1_coldft(const float* __restrict__ X) {
    __shared__ float cs[256], sn[256];
    int tid = threadIdx.x;
    {
        float s, c;
        sincospif((float)tid * (1.0f / 128.0f), &s, &c);  // angle 2*pi*tid/256
        cs[tid] = c;
        sn[tid] = s;
    }
    __syncthreads();

    int u = blockIdx.x, b = blockIdx.y;
    int i = tid & 63, g = tid >> 6;  // g handles ky = 4g .. 4g+3
    const float* xr = X + ((size_t)(b * RR + u) * RR) * CI + i;

    float x0 = xr[0];
    float x128 = xr[128 * CI];
    int kyb = g * 4;  // even -> parities 0,1,0,1
    float ar0 = x0 + x128, ar1 = x0 - x128, ar2 = x0 + x128, ar3 = x0 - x128;
    float ai0 = 0.f, ai1 = 0.f, ai2 = 0.f, ai3 = 0.f;

#pragma unroll 2
    for (int v = 1; v <= 127; ++v) {
        float xa = xr[v * CI];
        float xb = xr[(256 - v) * CI];
        float sm = xa + xb, df = xa - xb;
        int t0 = (kyb * v) & 255;
        int t1 = (t0 + v) & 255;
        int t2 = (t1 + v) & 255;
        int t3 = (t2 + v) & 255;
        ar0 += sm * cs[t0]; ai0 -= df * sn[t0];
        ar1 += sm * cs[t1]; ai1 -= df * sn[t1];
        ar2 += sm * cs[t2]; ai2 -= df * sn[t2];
        ar3 += sm * cs[t3]; ai3 -= df * sn[t3];
    }

    float2* ap = g_A + ((size_t)(b * MD + kyb) * RR + u) * CI + i;
    ap[0 * RR * CI] = make_float2(ar0, ai0);
    ap[1 * RR * CI] = make_float2(ar1, ai1);
    ap[2 * RR * CI] = make_float2(ar2, ai2);
    ap[3 * RR * CI] = make_float2(ar3, ai3);
}

// ---------------------------------------------------------------------------
// K2: partial row DFT along u for kx in {0..15, 240..255}.
// F[b][kxidx][ky][i] = sum_u A[b,ky,u,i] * exp(-2*pi*i*kx*u/256)
// u <-> 256-u symmetry with shared complex sum/diff.
// ---------------------------------------------------------------------------
__global__ __launch_bounds__(256) void k2_rowdft() {
    __shared__ float cs[256], sn[256];
    int tid = threadIdx.x;
    {
        float s, c;
        sincospif((float)tid * (1.0f / 128.0f), &s, &c);
        cs[tid] = c;
        sn[tid] = s;
    }
    __syncthreads();

    int ky = blockIdx.x, b = blockIdx.y;
    int i = tid & 63, g = tid >> 6;  // g handles kxidx = 8g .. 8g+7
    const float2* ap = g_A + ((size_t)(b * MD + ky) * RR) * CI + i;

    float Fr[8], Fi[8];
    float2 a0 = ap[0];
    float2 a128 = ap[128 * CI];
#pragma unroll
    for (int m = 0; m < 8; m++) {
        int idx = g * 8 + m;
        float sgn = (idx & 1) ? -1.0f : 1.0f;  // kx parity == idx parity (top & bottom)
        Fr[m] = a0.x + sgn * a128.x;
        Fi[m] = a0.y + sgn * a128.y;
    }

#pragma unroll 2
    for (int uu = 1; uu <= 127; ++uu) {
        float2 aa = ap[uu * CI];
        float2 ab = ap[(256 - uu) * CI];
        float prs = aa.x + ab.x, mrs = aa.x - ab.x;
        float pis = aa.y + ab.y, mis = aa.y - ab.y;
#pragma unroll
        for (int m = 0; m < 8; m++) {
            int idx = g * 8 + m;
            int kx = (idx < 16) ? idx : (224 + idx);  // 240..255
            int t = (kx * uu) & 255;
            float c = cs[t], s = sn[t];
            Fr[m] += prs * c + mis * s;
            Fi[m] += pis * c - mrs * s;
        }
    }

#pragma unroll
    for (int m = 0; m < 8; m++) {
        int idx = g * 8 + m;
        g_F[(((size_t)(b * KXN + idx) * MD) + ky) * CI + i] = make_float2(Fr[m], Fi[m]);
    }
}

// ---------------------------------------------------------------------------
// K3: channel mix (complex einsum over input channels) + ortho-norm fold.
// G[b][kxidx][ky][o] = (1/65536) * sum_i F[b][kxidx][ky][i] * W[i][o]
// W from fw0 (top, kxidx<16) or fw1 (bottom).
// ---------------------------------------------------------------------------
__global__ __launch_bounds__(256) void k3_mix(const float* __restrict__ fw0,
                                              const float* __restrict__ fw1) {
    __shared__ float2 ws[CI * CO];   // 32 KB
    __shared__ float2 fs[NB][CI];    // 4 KB
    int tid = threadIdx.x;
    int kxi = blockIdx.x, ky = blockIdx.y;
    const float* src = (kxi < 16) ? fw0 : fw1;
    int x = (kxi < 16) ? kxi : (kxi - 16);

    for (int p = tid; p < CI * CO; p += 256) {
        int i = p >> 6, o = p & 63;
        ws[p] = *(const float2*)(src + ((((size_t)i * CO + o) * MD + x) * MD + ky) * 2);
    }
    for (int p = tid; p < NB * CI; p += 256) {
        int bb = p >> 6, i = p & 63;
        fs[bb][i] = g_F[(((size_t)(bb * KXN + kxi) * MD) + ky) * CI + i];
    }
    __syncthreads();

    int o = tid & 63, bg = tid >> 6;
    const float scale = 1.0f / 65536.0f;  // ortho norm (1/256 fwd * 1/256 inv)
    for (int bb = bg; bb < NB; bb += 4) {
        float Gr = 0.f, Gi = 0.f;
#pragma unroll 8
        for (int i = 0; i < CI; i++) {
            float2 f = fs[bb][i];
            float2 w = ws[i * CO + o];
            Gr += f.x * w.x - f.y * w.y;
            Gi += f.x * w.y + f.y * w.x;
        }
        g_G[(((size_t)(bb * KXN + kxi) * MD) + ky) * CO + o] =
            make_float2(Gr * scale, Gi * scale);
    }
}

// ---------------------------------------------------------------------------
// K4: inverse DFT along kx (32 modes -> 256 u).
// H[b][ky][u][o] = sum_kxidx G[b][kxidx][ky][o] * exp(+2*pi*i*kx*u/256)
// ---------------------------------------------------------------------------
__global__ __launch_bounds__(256) void k4_invrow() {
    __shared__ float cs[256], sn[256];
    __shared__ float2 gs[KXN][CO];  // 16 KB
    int tid = threadIdx.x;
    {
        float s, c;
        sincospif((float)tid * (1.0f / 128.0f), &s, &c);
        cs[tid] = c;
        sn[tid] = s;
    }
    int ky = blockIdx.x, b = blockIdx.y;
    for (int p = tid; p < KXN * CO; p += 256) {
        int idx = p >> 6, o = p & 63;
        gs[idx][o] = g_G[(((size_t)(b * KXN + idx) * MD) + ky) * CO + o];
    }
    __syncthreads();

    int o = tid & 63, ug = tid >> 6;
    for (int uu = 0; uu < 64; ++uu) {
        int u = ug * 64 + uu;
        float Hrv = 0.f, Hiv = 0.f;
        int du = u & 255;
        int t = 0;  // kx = 0..15: t = kx*u mod 256
#pragma unroll
        for (int idx = 0; idx < 16; idx++) {
            float2 g2 = gs[idx][o];
            float c = cs[t], s = sn[t];
            Hrv += g2.x * c - g2.y * s;
            Hiv += g2.x * s + g2.y * c;
            t = (t + du) & 255;
        }
        t = (240 * u) & 255;  // kx = 240..255
#pragma unroll
        for (int idx = 16; idx < 32; idx++) {
            float2 g2 = gs[idx][o];
            float c = cs[t], s = sn[t];
            Hrv += g2.x * c - g2.y * s;
            Hiv += g2.x * s + g2.y * c;
            t = (t + du) & 255;
        }
        g_H[(((size_t)(b * MD + ky) * RR) + u) * CO + o] = make_float2(Hrv, Hiv);
    }
}

// ---------------------------------------------------------------------------
// K5: fused inverse real-DFT along ky (Hermitian, irfft semantics: DC imag
// discarded) + residual GEMM (X @ W_res + b_res) + SiLU.
// Packed f32x2 FMAs; 8v x 8o register tiles per thread.
// ---------------------------------------------------------------------------
#define SM5_WS 0
#define SM5_XS 4096                      // Xs[v][65] (padded: conflict-free)
#define SM5_HR (SM5_XS + 256 * 65)       // 20736
#define SM5_HI (SM5_HR + MD * CO)
#define SM5_CS (SM5_HI + MD * CO)
#define SM5_NS (SM5_CS + 256)
#define SM5_BR (SM5_NS + 256)
#define SM5_TOT (SM5_BR + 64)            // 23360 floats = 93440 bytes

__global__ __launch_bounds__(256, 2) void k5_final(const float* __restrict__ X,
                                                   const float* __restrict__ Wres,
                                                   const float* __restrict__ bres,
                                                   float* __restrict__ out) {
    extern __shared__ float sm[];
    float* Ws = sm + SM5_WS;
    float* Xs = sm + SM5_XS;
    float* Hr = sm + SM5_HR;
    float* Hi = sm + SM5_HI;
    float* cs2 = sm + SM5_CS;
    float* ns2 = sm + SM5_NS;
    float* br = sm + SM5_BR;

    int tid = threadIdx.x;
    int u = blockIdx.x, b = blockIdx.y;

    {
        float s, c;
        sincospif((float)tid * (1.0f / 128.0f), &s, &c);
        cs2[tid] = 2.0f * c;   // factor 2 folded (Hermitian pairs)
        ns2[tid] = -2.0f * s;
    }
    if (tid < 64) br[tid] = bres[tid];
    {
        const float4* w4 = (const float4*)Wres;
        float4* ws4 = (float4*)Ws;
        for (int p = tid; p < 1024; p += 256) ws4[p] = w4[p];
    }
    {
        const float4* x4 = (const float4*)(X + ((size_t)(b * RR + u) * RR) * CI);
        for (int p = tid; p < 4096; p += 256) {
            float4 xv = x4[p];
            int v = p >> 4;            // 16 float4 per v-row
            int c = (p & 15) * 4;
            float* d = Xs + v * 65 + c;
            d[0] = xv.x; d[1] = xv.y; d[2] = xv.z; d[3] = xv.w;
        }
    }
    for (int p = tid; p < MD * CO; p += 256) {
        int ky = p >> 6, o = p & 63;
        float2 h = g_H[(((size_t)(b * MD + ky) * RR) + u) * CO + o];
        Hr[p] = h.x;
        Hi[p] = h.y;
    }
    __syncthreads();

    int vg = tid >> 3, og = tid & 7;
    int v0 = vg * 8, o0 = og * 8;

    unsigned long long acc[4][8];
#pragma unroll
    for (int k = 0; k < 8; k++) {
        unsigned long long bb = pack2(br[o0 + k], br[o0 + k]);
#pragma unroll
        for (int p = 0; p < 4; p++) acc[p][k] = bb;
    }

    // Residual GEMM: acc[p][k] over v-pairs (v0+2p, v0+2p+1) x o (o0+k)
    const float* xb = Xs + v0 * 65;
#pragma unroll 4
    for (int c = 0; c < CI; c++) {
        unsigned long long xp0 = pack2(xb[c], xb[65 + c]);
        unsigned long long xp1 = pack2(xb[130 + c], xb[195 + c]);
        unsigned long long xp2 = pack2(xb[260 + c], xb[325 + c]);
        unsigned long long xp3 = pack2(xb[390 + c], xb[455 + c]);
        const float* wr = Ws + c * 64 + o0;
        float4 wa = *(const float4*)wr;
        float4 wb = *(const float4*)(wr + 4);
        float wv[8] = {wa.x, wa.y, wa.z, wa.w, wb.x, wb.y, wb.z, wb.w};
#pragma unroll
        for (int k = 0; k < 8; k++) {
            unsigned long long wd = pack2(wv[k], wv[k]);
            acc[0][k] = fma2(xp0, wd, acc[0][k]);
            acc[1][k] = fma2(xp1, wd, acc[1][k]);
            acc[2][k] = fma2(xp2, wd, acc[2][k]);
            acc[3][k] = fma2(xp3, wd, acc[3][k]);
        }
    }

    // Spectral ky = 0 term: + Re(H0[o]) (DC imag discarded, matches irfft)
#pragma unroll
    for (int k = 0; k < 8; k++) {
        unsigned long long h0 = pack2(Hr[o0 + k], Hr[o0 + k]);
#pragma unroll
        for (int p = 0; p < 4; p++) acc[p][k] = add2(acc[p][k], h0);
    }

    // Spectral ky = 1..15: + 2*(Hr*cos - Hi*sin)
    for (int ky = 1; ky < MD; ky++) {
        unsigned long long cp[4], sp[4];
#pragma unroll
        for (int p = 0; p < 4; p++) {
            int ta = (ky * (v0 + 2 * p)) & 255;
            int tb = (ta + ky) & 255;
            cp[p] = pack2(cs2[ta], cs2[tb]);
            sp[p] = pack2(ns2[ta], ns2[tb]);
        }
        const float* hrp = Hr + ky * 64 + o0;
        const float* hip = Hi + ky * 64 + o0;
#pragma unroll
        for (int k = 0; k < 8; k++) {
            unsigned long long hrd = pack2(hrp[k], hrp[k]);
            unsigned long long hid = pack2(hip[k], hip[k]);
#pragma unroll
            for (int p = 0; p < 4; p++) {
                acc[p][k] = fma2(hrd, cp[p], acc[p][k]);
                acc[p][k] = fma2(hid, sp[p], acc[p][k]);
            }
        }
    }

    // SiLU + store (float4)
    float* ob = out + (((size_t)(b * RR + u) * RR) + v0) * CO + o0;
#pragma unroll
    for (int p = 0; p < 4; p++) {
        float lo[8], hi[8];
#pragma unroll
        for (int k = 0; k < 8; k++) unpack2(acc[p][k], lo[k], hi[k]);
        float* r0 = ob + (size_t)(2 * p) * CO;
        float* r1 = ob + (size_t)(2 * p + 1) * CO;
        float4 a0 = make_float4(silu_f(lo[0]), silu_f(lo[1]), silu_f(lo[2]), silu_f(lo[3]));
        float4 a1 = make_float4(silu_f(lo[4]), silu_f(lo[5]), silu_f(lo[6]), silu_f(lo[7]));
        float4 b0 = make_float4(silu_f(hi[0]), silu_f(hi[1]), silu_f(hi[2]), silu_f(hi[3]));
        float4 b1 = make_float4(silu_f(hi[4]), silu_f(hi[5]), silu_f(hi[6]), silu_f(hi[7]));
        *(float4*)r0 = a0;
        *(float4*)(r0 + 4) = a1;
        *(float4*)r1 = b0;
        *(float4*)(r1 + 4) = b1;
    }
}

// ---------------------------------------------------------------------------
// Launcher
// ---------------------------------------------------------------------------
extern "C" void kernel_launch(void* const* d_in, const int* in_sizes, int n_in,
                              void* d_out, int out_size) {
    const float* X = (const float*)d_in[0];
    const float* Wres = (const float*)d_in[1];
    const float* bres = (const float*)d_in[2];
    const float* fw0 = (const float*)d_in[3];
    const float* fw1 = (const float*)d_in[4];
    float* out = (float*)d_out;

    cudaFuncSetAttribute(k5_final, cudaFuncAttributeMaxDynamicSharedMemorySize,
                         SM5_TOT * (int)sizeof(float));

    k1_coldft<<<dim3(RR, NB), 256>>>(X);
    k2_rowdft<<<dim3(MD, NB), 256>>>();
    k3_mix<<<dim3(KXN, MD), 256>>>(fw0, fw1);
    k4_invrow<<<dim3(MD, NB), 256>>>();
    k5_final<<<dim3(RR, NB), 256, SM5_TOT * (int)sizeof(float)>>>(X, Wres, bres, out);
}